// round 1
// baseline (speedup 1.0000x reference)
#include <cuda_runtime.h>
#include <cuda_bf16.h>

#define N_NODES 10000
#define N_EDGES 640000
#define D 128

// ---------------- scratch (static device globals; no allocation) ----------------
__device__ int   g_deg[N_NODES];
__device__ int   g_cursor[N_NODES];
__device__ int   g_rowstart[N_NODES + 1];
__device__ int   g_csr_src[N_EDGES];
__device__ float g_inv[N_NODES];
__device__ float g_agg[(size_t)N_NODES * D];
__device__ float g_h1[(size_t)N_NODES * D];
__device__ float g_h2[(size_t)N_NODES * D];
__device__ float g_ps[N_NODES * 2];
__device__ float g_pd[N_NODES * 2];

// ---------------- CSR build ----------------
__global__ void k_zero() {
    int i = blockIdx.x * blockDim.x + threadIdx.x;
    if (i < N_NODES) { g_deg[i] = 0; g_cursor[i] = 0; }
}

__global__ void k_count(const int* __restrict__ dst) {
    int e = blockIdx.x * blockDim.x + threadIdx.x;
    if (e < N_EDGES) atomicAdd(&g_deg[dst[e]], 1);
}

#define SCAN_T 1024
#define CHUNK 10   // 1024*10 >= 10000
__global__ void k_scan() {
    __shared__ int sh[SCAN_T];
    int t = threadIdx.x;
    int base = t * CHUNK;
    int local[CHUNK];
    int run = 0;
#pragma unroll
    for (int i = 0; i < CHUNK; i++) {
        int idx = base + i;
        int d = (idx < N_NODES) ? g_deg[idx] : 0;
        local[i] = run;
        run += d;
    }
    sh[t] = run;
    __syncthreads();
    for (int off = 1; off < SCAN_T; off <<= 1) {
        int v = (t >= off) ? sh[t - off] : 0;
        __syncthreads();
        sh[t] += v;
        __syncthreads();
    }
    int chunkbase = sh[t] - run;  // exclusive prefix of this chunk
#pragma unroll
    for (int i = 0; i < CHUNK; i++) {
        int idx = base + i;
        if (idx < N_NODES) {
            g_rowstart[idx] = chunkbase + local[i];
            int d = g_deg[idx];
            g_inv[idx] = 1.0f / (float)(d > 1 ? d : 1);
        }
    }
    if (t == SCAN_T - 1) g_rowstart[N_NODES] = sh[t];
}

__global__ void k_fill(const int* __restrict__ src, const int* __restrict__ dst) {
    int e = blockIdx.x * blockDim.x + threadIdx.x;
    if (e < N_EDGES) {
        int d = dst[e];
        int pos = atomicAdd(&g_cursor[d], 1);
        g_csr_src[g_rowstart[d] + pos] = src[e];
    }
}

// ---------------- mean aggregation: one warp per node, pull-style ----------------
__global__ void k_agg(const float* __restrict__ feat, float* __restrict__ out) {
    int gid = blockIdx.x * blockDim.x + threadIdx.x;
    int warp = gid >> 5;
    int lane = gid & 31;
    if (warp >= N_NODES) return;
    int start = g_rowstart[warp];
    int end   = g_rowstart[warp + 1];

    float4 a0 = make_float4(0.f, 0.f, 0.f, 0.f);
    float4 a1 = a0, a2 = a0, a3 = a0;
    int j = start;
    for (; j + 4 <= end; j += 4) {
        int s0 = g_csr_src[j + 0];
        int s1 = g_csr_src[j + 1];
        int s2 = g_csr_src[j + 2];
        int s3 = g_csr_src[j + 3];
        float4 v0 = *(const float4*)(feat + (size_t)s0 * D + lane * 4);
        float4 v1 = *(const float4*)(feat + (size_t)s1 * D + lane * 4);
        float4 v2 = *(const float4*)(feat + (size_t)s2 * D + lane * 4);
        float4 v3 = *(const float4*)(feat + (size_t)s3 * D + lane * 4);
        a0.x += v0.x; a0.y += v0.y; a0.z += v0.z; a0.w += v0.w;
        a1.x += v1.x; a1.y += v1.y; a1.z += v1.z; a1.w += v1.w;
        a2.x += v2.x; a2.y += v2.y; a2.z += v2.z; a2.w += v2.w;
        a3.x += v3.x; a3.y += v3.y; a3.z += v3.z; a3.w += v3.w;
    }
    for (; j < end; j++) {
        int s = g_csr_src[j];
        float4 v = *(const float4*)(feat + (size_t)s * D + lane * 4);
        a0.x += v.x; a0.y += v.y; a0.z += v.z; a0.w += v.w;
    }
    float inv = g_inv[warp];
    float4 r;
    r.x = (a0.x + a1.x + a2.x + a3.x) * inv;
    r.y = (a0.y + a1.y + a2.y + a3.y) * inv;
    r.z = (a0.z + a1.z + a2.z + a3.z) * inv;
    r.w = (a0.w + a1.w + a2.w + a3.w) * inv;
    *(float4*)(out + (size_t)warp * D + lane * 4) = r;
}

// ---------------- fused SAGE layer: out = act(X@Ws + A@Wn + b) ----------------
// Tile: 32 rows x 128 cols per block, 128 threads. K=128 per operand, 2 operands.
#define TM 32
__global__ __launch_bounds__(128) void k_layer(
    const float* __restrict__ X, const float* __restrict__ A,
    const float* __restrict__ Ws, const float* __restrict__ Wn,
    const float* __restrict__ bias, float* __restrict__ out, int doRelu)
{
    __shared__ float sW[32][128];
    __shared__ float sA[TM][32];
    int t = threadIdx.x;
    int warp = t >> 5;
    int lane = t & 31;
    int row0 = blockIdx.x * TM;

    float acc[8][4];
#pragma unroll
    for (int i = 0; i < 8; i++)
#pragma unroll
        for (int c = 0; c < 4; c++) acc[i][c] = 0.f;

    for (int op = 0; op < 2; op++) {
        const float* M = op ? A : X;
        const float* W = op ? Wn : Ws;
        for (int kt = 0; kt < 128; kt += 32) {
            // stage W tile [32][128]: 1024 float4, 8 per thread
#pragma unroll
            for (int i = 0; i < 8; i++) {
                int f4 = t + i * 128;
                int kk = f4 >> 5;
                int c4 = f4 & 31;
                *(float4*)&sW[kk][c4 << 2] =
                    *(const float4*)(W + (size_t)(kt + kk) * 128 + (c4 << 2));
            }
            // stage A tile [32][32]: 256 float4, 2 per thread
#pragma unroll
            for (int i = 0; i < 2; i++) {
                int f4 = t + i * 128;
                int r = f4 >> 3;
                int c4 = f4 & 7;
                int grow = row0 + r;
                float4 v = make_float4(0.f, 0.f, 0.f, 0.f);
                if (grow < N_NODES)
                    v = *(const float4*)(M + (size_t)grow * 128 + kt + (c4 << 2));
                *(float4*)&sA[r][c4 << 2] = v;
            }
            __syncthreads();
#pragma unroll
            for (int kk = 0; kk < 32; kk++) {
                float4 w4 = *(float4*)&sW[kk][lane << 2];
#pragma unroll
                for (int i = 0; i < 8; i++) {
                    float a = sA[warp * 8 + i][kk];
                    acc[i][0] += a * w4.x;
                    acc[i][1] += a * w4.y;
                    acc[i][2] += a * w4.z;
                    acc[i][3] += a * w4.w;
                }
            }
            __syncthreads();
        }
    }

    float4 bv = *(const float4*)(bias + (lane << 2));
#pragma unroll
    for (int i = 0; i < 8; i++) {
        int grow = row0 + warp * 8 + i;
        if (grow < N_NODES) {
            float4 r;
            r.x = acc[i][0] + bv.x;
            r.y = acc[i][1] + bv.y;
            r.z = acc[i][2] + bv.z;
            r.w = acc[i][3] + bv.w;
            if (doRelu) {
                r.x = fmaxf(r.x, 0.f); r.y = fmaxf(r.y, 0.f);
                r.z = fmaxf(r.z, 0.f); r.w = fmaxf(r.w, 0.f);
            }
            *(float4*)(out + (size_t)grow * 128 + (lane << 2)) = r;
        }
    }
}

// ---------------- per-node predictor halves: ps = h2@Wp[0:128] + b, pd = h2@Wp[128:256]
__global__ void k_pred(const float* __restrict__ h2, const float* __restrict__ Wp,
                       const float* __restrict__ bp) {
    int gid = blockIdx.x * blockDim.x + threadIdx.x;
    int warp = gid >> 5;
    int lane = gid & 31;
    if (warp >= N_NODES) return;
    float4 h = *(const float4*)(h2 + (size_t)warp * 128 + lane * 4);
    int d = lane * 4;
    // W_pred row-major [256,2]; rows d..d+3 top half
    float4 wa = *(const float4*)(Wp + d * 2);        // (d,c0)(d,c1)(d+1,c0)(d+1,c1)
    float4 wb = *(const float4*)(Wp + d * 2 + 4);    // (d+2,..)(d+3,..)
    float4 wc = *(const float4*)(Wp + (128 + d) * 2);
    float4 wd_ = *(const float4*)(Wp + (128 + d) * 2 + 4);
    float s0 = h.x * wa.x + h.y * wa.z + h.z * wb.x + h.w * wb.z;
    float s1 = h.x * wa.y + h.y * wa.w + h.z * wb.y + h.w * wb.w;
    float t0 = h.x * wc.x + h.y * wc.z + h.z * wd_.x + h.w * wd_.z;
    float t1 = h.x * wc.y + h.y * wc.w + h.z * wd_.y + h.w * wd_.w;
#pragma unroll
    for (int off = 16; off > 0; off >>= 1) {
        s0 += __shfl_xor_sync(0xFFFFFFFF, s0, off);
        s1 += __shfl_xor_sync(0xFFFFFFFF, s1, off);
        t0 += __shfl_xor_sync(0xFFFFFFFF, t0, off);
        t1 += __shfl_xor_sync(0xFFFFFFFF, t1, off);
    }
    if (lane == 0) {
        g_ps[warp * 2 + 0] = s0 + bp[0];
        g_ps[warp * 2 + 1] = s1 + bp[1];
        g_pd[warp * 2 + 0] = t0;
        g_pd[warp * 2 + 1] = t1;
    }
}

// ---------------- edge scores: out[e] = ps[src[e]] + pd[dst[e]] ----------------
__global__ void k_edge(const int* __restrict__ src, const int* __restrict__ dst,
                       float* __restrict__ out) {
    int e = blockIdx.x * blockDim.x + threadIdx.x;
    if (e >= N_EDGES) return;
    int s = src[e];
    int d = dst[e];
    float2 p = *(const float2*)(g_ps + s * 2);
    float2 q = *(const float2*)(g_pd + d * 2);
    float2 r;
    r.x = p.x + q.x;
    r.y = p.y + q.y;
    ((float2*)out)[e] = r;
}

// ---------------- launch ----------------
extern "C" void kernel_launch(void* const* d_in, const int* in_sizes, int n_in,
                              void* d_out, int out_size) {
    const float* x       = (const float*)d_in[0];
    const int*   src     = (const int*)d_in[1];
    const int*   dst     = (const int*)d_in[2];
    const float* W_self1 = (const float*)d_in[3];
    const float* W_neigh1= (const float*)d_in[4];
    const float* b1      = (const float*)d_in[5];
    const float* W_self2 = (const float*)d_in[6];
    const float* W_neigh2= (const float*)d_in[7];
    const float* b2      = (const float*)d_in[8];
    const float* W_pred  = (const float*)d_in[9];
    const float* b_pred  = (const float*)d_in[10];
    float* out = (float*)d_out;

    float* agg; cudaGetSymbolAddress((void**)&agg, g_agg);
    float* h1;  cudaGetSymbolAddress((void**)&h1,  g_h1);
    float* h2;  cudaGetSymbolAddress((void**)&h2,  g_h2);

    const int TB = 256;
    // CSR build
    k_zero<<<(N_NODES + TB - 1) / TB, TB>>>();
    k_count<<<(N_EDGES + TB - 1) / TB, TB>>>(dst);
    k_scan<<<1, SCAN_T>>>();
    k_fill<<<(N_EDGES + TB - 1) / TB, TB>>>(src, dst);

    int aggBlocks = (N_NODES * 32 + TB - 1) / TB;
    int gemmBlocks = (N_NODES + TM - 1) / TM;

    // layer 1
    k_agg<<<aggBlocks, TB>>>(x, agg);
    k_layer<<<gemmBlocks, 128>>>(x, agg, W_self1, W_neigh1, b1, h1, 1);
    // layer 2
    k_agg<<<aggBlocks, TB>>>(h1, agg);
    k_layer<<<gemmBlocks, 128>>>(h1, agg, W_self2, W_neigh2, b2, h2, 0);
    // predictor
    k_pred<<<aggBlocks, TB>>>(h2, W_pred, b_pred);
    k_edge<<<(N_EDGES + TB - 1) / TB, TB>>>(src, dst, out);
}

// round 2
// speedup vs baseline: 1.0424x; 1.0424x over previous
#include <cuda_runtime.h>
#include <cuda_fp16.h>
#include <cuda_bf16.h>

#define N_NODES 10000
#define N_EDGES 640000
#define D 128

// ---------------- scratch (static device globals; no allocation) ----------------
__device__ int   g_deg[N_NODES];
__device__ int   g_cursor[N_NODES];
__device__ int   g_rowstart[N_NODES + 1];
__device__ int   g_csr_src[N_EDGES];
__device__ float g_inv[N_NODES];
__device__ float g_S[(size_t)N_NODES * D];    // self-path result (fp32)
__device__ __half g_P[(size_t)N_NODES * D];   // neigh-path projection (fp16, gathered)
__device__ float g_h1[(size_t)N_NODES * D];
__device__ float g_ps[N_NODES * 2];
__device__ float g_pd[N_NODES * 2];

// ---------------- CSR build ----------------
__global__ void k_zero() {
    int i = blockIdx.x * blockDim.x + threadIdx.x;
    if (i < N_NODES) g_deg[i] = 0;
}

__global__ void k_count(const int* __restrict__ dst) {
    int i = blockIdx.x * blockDim.x + threadIdx.x;
    if (i < N_EDGES / 4) {
        int4 d = ((const int4*)dst)[i];
        atomicAdd(&g_deg[d.x], 1);
        atomicAdd(&g_deg[d.y], 1);
        atomicAdd(&g_deg[d.z], 1);
        atomicAdd(&g_deg[d.w], 1);
    }
}

#define SCAN_T 1024
#define CHUNK 10   // 1024*10 >= 10000
__global__ void k_scan() {
    __shared__ int sh[SCAN_T];
    int t = threadIdx.x;
    int base = t * CHUNK;
    int local[CHUNK];
    int run = 0;
#pragma unroll
    for (int i = 0; i < CHUNK; i++) {
        int idx = base + i;
        int d = (idx < N_NODES) ? g_deg[idx] : 0;
        local[i] = run;
        run += d;
    }
    sh[t] = run;
    __syncthreads();
    for (int off = 1; off < SCAN_T; off <<= 1) {
        int v = (t >= off) ? sh[t - off] : 0;
        __syncthreads();
        sh[t] += v;
        __syncthreads();
    }
    int chunkbase = sh[t] - run;  // exclusive prefix of this chunk
#pragma unroll
    for (int i = 0; i < CHUNK; i++) {
        int idx = base + i;
        if (idx < N_NODES) {
            int rs = chunkbase + local[i];
            g_rowstart[idx] = rs;
            g_cursor[idx]   = rs;          // cursor starts at rowstart
            int d = g_deg[idx];
            g_inv[idx] = 1.0f / (float)(d > 1 ? d : 1);
        }
    }
    if (t == SCAN_T - 1) g_rowstart[N_NODES] = sh[t];
}

__global__ void k_fill(const int* __restrict__ src, const int* __restrict__ dst) {
    int i = blockIdx.x * blockDim.x + threadIdx.x;
    if (i < N_EDGES / 4) {
        int4 s = ((const int4*)src)[i];
        int4 d = ((const int4*)dst)[i];
        int p0 = atomicAdd(&g_cursor[d.x], 1);
        int p1 = atomicAdd(&g_cursor[d.y], 1);
        int p2 = atomicAdd(&g_cursor[d.z], 1);
        int p3 = atomicAdd(&g_cursor[d.w], 1);
        g_csr_src[p0] = s.x;
        g_csr_src[p1] = s.y;
        g_csr_src[p2] = s.z;
        g_csr_src[p3] = s.w;
    }
}

// ---------------- fused projection: [S | P] = X @ [Wa | Wb], S += bias ----------------
// 72 rows x 256 cols per block, 256 threads (8 warps x 9 rows, lane -> 4+4 cols)
#define PM 72
__global__ __launch_bounds__(256) void k_proj(
    const float* __restrict__ X,
    const float* __restrict__ Wa, const float* __restrict__ Wb,
    const float* __restrict__ bias,
    float* __restrict__ S, __half* __restrict__ P)
{
    __shared__ float sX[PM][32];
    __shared__ float sWa[32][128];
    __shared__ float sWb[32][128];
    int t = threadIdx.x;
    int warp = t >> 5;
    int lane = t & 31;
    int row0 = blockIdx.x * PM;

    float acc[9][8];
#pragma unroll
    for (int i = 0; i < 9; i++)
#pragma unroll
        for (int c = 0; c < 8; c++) acc[i][c] = 0.f;

    for (int kt = 0; kt < 128; kt += 32) {
        // stage Wa, Wb tiles: [32][128] each = 1024 float4, 4 per thread
#pragma unroll
        for (int i = 0; i < 4; i++) {
            int f4 = t + i * 256;
            int kk = f4 >> 5;
            int c4 = f4 & 31;
            ((float4*)&sWa[kk][0])[c4] = ((const float4*)(Wa + (size_t)(kt + kk) * 128))[c4];
            ((float4*)&sWb[kk][0])[c4] = ((const float4*)(Wb + (size_t)(kt + kk) * 128))[c4];
        }
        // stage X tile: [72][32] = 576 float4
#pragma unroll
        for (int i = 0; i < 3; i++) {
            int f4 = t + i * 256;
            if (f4 < PM * 8) {
                int r = f4 >> 3;
                int c4 = f4 & 7;
                int grow = row0 + r;
                float4 v = make_float4(0.f, 0.f, 0.f, 0.f);
                if (grow < N_NODES)
                    v = ((const float4*)(X + (size_t)grow * 128 + kt))[c4];
                ((float4*)&sX[r][0])[c4] = v;
            }
        }
        __syncthreads();
#pragma unroll
        for (int kk = 0; kk < 32; kk++) {
            float4 wa4 = ((float4*)&sWa[kk][0])[lane];
            float4 wb4 = ((float4*)&sWb[kk][0])[lane];
#pragma unroll
            for (int i = 0; i < 9; i++) {
                float a = sX[warp * 9 + i][kk];
                acc[i][0] += a * wa4.x;
                acc[i][1] += a * wa4.y;
                acc[i][2] += a * wa4.z;
                acc[i][3] += a * wa4.w;
                acc[i][4] += a * wb4.x;
                acc[i][5] += a * wb4.y;
                acc[i][6] += a * wb4.z;
                acc[i][7] += a * wb4.w;
            }
        }
        __syncthreads();
    }

    float4 bv = ((const float4*)bias)[lane];
#pragma unroll
    for (int i = 0; i < 9; i++) {
        int grow = row0 + warp * 9 + i;
        if (grow < N_NODES) {
            float4 s;
            s.x = acc[i][0] + bv.x;
            s.y = acc[i][1] + bv.y;
            s.z = acc[i][2] + bv.z;
            s.w = acc[i][3] + bv.w;
            ((float4*)(S + (size_t)grow * 128))[lane] = s;
            __half2 p01 = __floats2half2_rn(acc[i][4], acc[i][5]);
            __half2 p23 = __floats2half2_rn(acc[i][6], acc[i][7]);
            uint2 pk;
            pk.x = *(unsigned int*)&p01;
            pk.y = *(unsigned int*)&p23;
            *(uint2*)(P + (size_t)grow * 128 + lane * 4) = pk;
        }
    }
}

// ---------------- agg + epilogue helpers ----------------
__device__ __forceinline__ void warp_gather_sum(const __half* __restrict__ P,
                                                int start, int end, int lane,
                                                float& r0, float& r1, float& r2, float& r3)
{
    float a0 = 0.f, a1 = 0.f, a2 = 0.f, a3 = 0.f;
    float b0 = 0.f, b1 = 0.f, b2 = 0.f, b3 = 0.f;
    float c0 = 0.f, c1 = 0.f, c2 = 0.f, c3 = 0.f;
    float d0 = 0.f, d1 = 0.f, d2 = 0.f, d3 = 0.f;
    int j = start;
    for (; j + 4 <= end; j += 4) {
        int s0 = g_csr_src[j + 0];
        int s1 = g_csr_src[j + 1];
        int s2 = g_csr_src[j + 2];
        int s3 = g_csr_src[j + 3];
        uint2 v0 = *(const uint2*)(P + (size_t)s0 * D + lane * 4);
        uint2 v1 = *(const uint2*)(P + (size_t)s1 * D + lane * 4);
        uint2 v2 = *(const uint2*)(P + (size_t)s2 * D + lane * 4);
        uint2 v3 = *(const uint2*)(P + (size_t)s3 * D + lane * 4);
        float2 f;
        f = __half22float2(*(__half2*)&v0.x); a0 += f.x; a1 += f.y;
        f = __half22float2(*(__half2*)&v0.y); a2 += f.x; a3 += f.y;
        f = __half22float2(*(__half2*)&v1.x); b0 += f.x; b1 += f.y;
        f = __half22float2(*(__half2*)&v1.y); b2 += f.x; b3 += f.y;
        f = __half22float2(*(__half2*)&v2.x); c0 += f.x; c1 += f.y;
        f = __half22float2(*(__half2*)&v2.y); c2 += f.x; c3 += f.y;
        f = __half22float2(*(__half2*)&v3.x); d0 += f.x; d1 += f.y;
        f = __half22float2(*(__half2*)&v3.y); d2 += f.x; d3 += f.y;
    }
    for (; j < end; j++) {
        int s = g_csr_src[j];
        uint2 v = *(const uint2*)(P + (size_t)s * D + lane * 4);
        float2 f;
        f = __half22float2(*(__half2*)&v.x); a0 += f.x; a1 += f.y;
        f = __half22float2(*(__half2*)&v.y); a2 += f.x; a3 += f.y;
    }
    r0 = (a0 + b0) + (c0 + d0);
    r1 = (a1 + b1) + (c1 + d1);
    r2 = (a2 + b2) + (c2 + d2);
    r3 = (a3 + b3) + (c3 + d3);
}

// layer 1: H = relu(S + inv * sum P[neighbors])
__global__ void k_aggfuse_relu(const __half* __restrict__ P,
                               const float* __restrict__ S,
                               float* __restrict__ H)
{
    int gid = blockIdx.x * blockDim.x + threadIdx.x;
    int node = gid >> 5;
    int lane = gid & 31;
    if (node >= N_NODES) return;
    float r0, r1, r2, r3;
    warp_gather_sum(P, g_rowstart[node], g_rowstart[node + 1], lane, r0, r1, r2, r3);
    float inv = g_inv[node];
    float4 s4 = ((const float4*)(S + (size_t)node * D))[lane];
    float4 o;
    o.x = fmaxf(s4.x + r0 * inv, 0.f);
    o.y = fmaxf(s4.y + r1 * inv, 0.f);
    o.z = fmaxf(s4.z + r2 * inv, 0.f);
    o.w = fmaxf(s4.w + r3 * inv, 0.f);
    ((float4*)(H + (size_t)node * D))[lane] = o;
}

// layer 2 + predictor: h2 = S + inv*sum; ps/pd = h2 . Wp halves (+ bias)
__global__ void k_aggfuse_pred(const __half* __restrict__ P,
                               const float* __restrict__ S,
                               const float* __restrict__ Wp,
                               const float* __restrict__ bp)
{
    int gid = blockIdx.x * blockDim.x + threadIdx.x;
    int node = gid >> 5;
    int lane = gid & 31;
    if (node >= N_NODES) return;
    float r0, r1, r2, r3;
    warp_gather_sum(P, g_rowstart[node], g_rowstart[node + 1], lane, r0, r1, r2, r3);
    float inv = g_inv[node];
    float4 s4 = ((const float4*)(S + (size_t)node * D))[lane];
    float h0 = s4.x + r0 * inv;
    float h1 = s4.y + r1 * inv;
    float h2 = s4.z + r2 * inv;
    float h3 = s4.w + r3 * inv;

    int d = lane * 4;
    // W_pred row-major [256,2]
    float4 wa = *(const float4*)(Wp + d * 2);         // rows d, d+1 (both cls)
    float4 wb = *(const float4*)(Wp + d * 2 + 4);     // rows d+2, d+3
    float4 wc = *(const float4*)(Wp + (128 + d) * 2);
    float4 wd_ = *(const float4*)(Wp + (128 + d) * 2 + 4);
    float s0 = h0 * wa.x + h1 * wa.z + h2 * wb.x + h3 * wb.z;
    float s1 = h0 * wa.y + h1 * wa.w + h2 * wb.y + h3 * wb.w;
    float t0 = h0 * wc.x + h1 * wc.z + h2 * wd_.x + h3 * wd_.z;
    float t1 = h0 * wc.y + h1 * wc.w + h2 * wd_.y + h3 * wd_.w;
#pragma unroll
    for (int off = 16; off > 0; off >>= 1) {
        s0 += __shfl_xor_sync(0xFFFFFFFF, s0, off);
        s1 += __shfl_xor_sync(0xFFFFFFFF, s1, off);
        t0 += __shfl_xor_sync(0xFFFFFFFF, t0, off);
        t1 += __shfl_xor_sync(0xFFFFFFFF, t1, off);
    }
    if (lane == 0) {
        g_ps[node * 2 + 0] = s0 + bp[0];
        g_ps[node * 2 + 1] = s1 + bp[1];
        g_pd[node * 2 + 0] = t0;
        g_pd[node * 2 + 1] = t1;
    }
}

// ---------------- edge scores: out[e] = ps[src[e]] + pd[dst[e]], 2 edges/thread ----------------
__global__ void k_edge(const int* __restrict__ src, const int* __restrict__ dst,
                       float* __restrict__ out) {
    int i = blockIdx.x * blockDim.x + threadIdx.x;
    if (i >= N_EDGES / 2) return;
    int2 s = ((const int2*)src)[i];
    int2 d = ((const int2*)dst)[i];
    float2 p0 = *(const float2*)(g_ps + s.x * 2);
    float2 p1 = *(const float2*)(g_ps + s.y * 2);
    float2 q0 = *(const float2*)(g_pd + d.x * 2);
    float2 q1 = *(const float2*)(g_pd + d.y * 2);
    float4 o;
    o.x = p0.x + q0.x;
    o.y = p0.y + q0.y;
    o.z = p1.x + q1.x;
    o.w = p1.y + q1.y;
    ((float4*)out)[i] = o;
}

// ---------------- launch ----------------
extern "C" void kernel_launch(void* const* d_in, const int* in_sizes, int n_in,
                              void* d_out, int out_size) {
    const float* x       = (const float*)d_in[0];
    const int*   src     = (const int*)d_in[1];
    const int*   dst     = (const int*)d_in[2];
    const float* W_self1 = (const float*)d_in[3];
    const float* W_neigh1= (const float*)d_in[4];
    const float* b1      = (const float*)d_in[5];
    const float* W_self2 = (const float*)d_in[6];
    const float* W_neigh2= (const float*)d_in[7];
    const float* b2      = (const float*)d_in[8];
    const float* W_pred  = (const float*)d_in[9];
    const float* b_pred  = (const float*)d_in[10];
    float* out = (float*)d_out;

    float*  S;  cudaGetSymbolAddress((void**)&S,  g_S);
    __half* P;  cudaGetSymbolAddress((void**)&P,  g_P);
    float*  h1; cudaGetSymbolAddress((void**)&h1, g_h1);

    const int TB = 256;
    // CSR build
    k_zero<<<(N_NODES + TB - 1) / TB, TB>>>();
    k_count<<<(N_EDGES / 4 + TB - 1) / TB, TB>>>(dst);
    k_scan<<<1, SCAN_T>>>();
    k_fill<<<(N_EDGES / 4 + TB - 1) / TB, TB>>>(src, dst);

    int aggBlocks  = (N_NODES * 32 + TB - 1) / TB;
    int projBlocks = (N_NODES + PM - 1) / PM;

    // layer 1: [S|P] = x @ [Ws1|Wn1], then h1 = relu(S + agg(P))
    k_proj<<<projBlocks, 256>>>(x, W_self1, W_neigh1, b1, S, P);
    k_aggfuse_relu<<<aggBlocks, TB>>>(P, S, h1);
    // layer 2 + predictor
    k_proj<<<projBlocks, 256>>>(h1, W_self2, W_neigh2, b2, S, P);
    k_aggfuse_pred<<<aggBlocks, TB>>>(P, S, W_pred, b_pred);
    // edge scores
    k_edge<<<(N_EDGES / 2 + TB - 1) / TB, TB>>>(src, dst, out);
}